// round 1
// baseline (speedup 1.0000x reference)
#include <cuda_runtime.h>

#define IMG 1024
#define NPIX (IMG*IMG)

// Persistent state (allocation-free scratch): 3 h buffers (ping, pong, enc-final
// held as constant decoder input) + 2 c buffers.
__device__ __align__(16) float g_h[3][NPIX];
__device__ __align__(16) float g_c[2][NPIX];

// [0] = encoder, [1] = decoder. w layout [o][ch][ky][kx] flattened (o*18+ch*9+ky*3+kx)
__constant__ float c_w[2][72];
__constant__ float c_b[2][4];

__device__ __forceinline__ float sigf(float x){
    // 1/(1+e^-x) via MUFU EX2 + RCP (approx div). ~2 ulp, fine vs 1e-3 gate.
    return __fdividef(1.0f, 1.0f + __expf(-x));
}
__device__ __forceinline__ float tanhf_fast(float x){
    // tanh(x) = 2*sigmoid(2x) - 1  (exact identity; abs err ~1e-7)
    return 2.0f * __fdividef(1.0f, 1.0f + __expf(-2.0f*x)) - 1.0f;
}

// One ConvLSTM cell step over the full 1024x1024 image.
// gates = conv3x3(concat(x, h_prev)) + b ; i,f,o,g = gates[0..3]
// c = sig(f)*c_prev + sig(i)*tanh(g) ; h = sig(o)*tanh(c)
// FIRST: h_prev = c_prev = 0 (skip their loads / terms entirely).
template<bool FIRST>
__global__ __launch_bounds__(256, 2)
void lstm_step(const float* __restrict__ x,
               const float* __restrict__ hprev,
               const float* __restrict__ cprev,
               float* __restrict__ hout,
               float* __restrict__ cout,
               int wsel)
{
    // s[ch][row-1..row+1][col], col stored at index col+4 so float4 loads at
    // 4t land 16B-aligned. Index 3 = col -1 (zero), index 1028 = col 1024 (zero).
    __shared__ __align__(16) float s[2][3][1032];

    const int t   = threadIdx.x;
    const int row = blockIdx.x;

    // Stage 3 rows of x (and h) into smem, zero-filled outside the image.
    #pragma unroll
    for (int rr = 0; rr < 3; ++rr){
        int gy = row - 1 + rr;
        float4 vx = make_float4(0.f, 0.f, 0.f, 0.f);
        float4 vh = vx;
        if ((unsigned)gy < IMG){
            vx = *(const float4*)(x + (size_t)gy*IMG + 4*t);
            if (!FIRST) vh = *(const float4*)(hprev + (size_t)gy*IMG + 4*t);
        }
        *(float4*)&s[0][rr][4 + 4*t] = vx;
        if (!FIRST) *(float4*)&s[1][rr][4 + 4*t] = vh;
    }
    if (t < 6){
        s[t & 1][t >> 1][3]    = 0.f;   // col -1
        s[t & 1][t >> 1][1028] = 0.f;   // col 1024
    }
    __syncthreads();

    const float* W = c_w[wsel];

    float acc[4][4];
    #pragma unroll
    for (int o = 0; o < 4; ++o){
        float bo = c_b[wsel][o];
        #pragma unroll
        for (int p = 0; p < 4; ++p) acc[o][p] = bo;
    }

    const int col4 = 4 * t;   // this thread owns pixels col4 .. col4+3

    #pragma unroll
    for (int ch = 0; ch < 2; ++ch){
        if (FIRST && ch == 1) break;   // h_prev == 0 contributes nothing
        #pragma unroll
        for (int r = 0; r < 3; ++r){
            const float* srow = s[ch][r];
            float  v0 = srow[col4 + 3];
            float4 vm = *(const float4*)&srow[col4 + 4];
            float  v5 = srow[col4 + 8];
            float v[6] = {v0, vm.x, vm.y, vm.z, vm.w, v5};
            #pragma unroll
            for (int o = 0; o < 4; ++o){
                const float w0 = W[o*18 + ch*9 + r*3 + 0];
                const float w1 = W[o*18 + ch*9 + r*3 + 1];
                const float w2 = W[o*18 + ch*9 + r*3 + 2];
                #pragma unroll
                for (int p = 0; p < 4; ++p)
                    acc[o][p] = fmaf(v[p+2], w2,
                                fmaf(v[p+1], w1,
                                fmaf(v[p  ], w0, acc[o][p])));
            }
        }
    }

    const int base = row * IMG + col4;

    float4 cp = make_float4(0.f, 0.f, 0.f, 0.f);
    if (!FIRST) cp = *(const float4*)(cprev + base);
    const float cpv[4] = {cp.x, cp.y, cp.z, cp.w};

    float hn[4], cn[4];
    #pragma unroll
    for (int p = 0; p < 4; ++p){
        const float iv = sigf(acc[0][p]);
        const float fv = sigf(acc[1][p]);
        const float ov = sigf(acc[2][p]);
        const float gv = tanhf_fast(acc[3][p]);
        const float ig = iv * gv;
        const float c2 = FIRST ? ig : fmaf(fv, cpv[p], ig);
        cn[p] = c2;
        hn[p] = ov * tanhf_fast(c2);
    }

    *(float4*)(cout + base) = make_float4(cn[0], cn[1], cn[2], cn[3]);
    *(float4*)(hout + base) = make_float4(hn[0], hn[1], hn[2], hn[3]);
}

extern "C" void kernel_launch(void* const* d_in, const int* in_sizes, int n_in,
                              void* d_out, int out_size)
{
    (void)in_sizes; (void)n_in; (void)out_size;

    const float* data  = (const float*)d_in[0];   // [20,1,1,1024,1024]
    const float* enc_w = (const float*)d_in[1];   // [4,2,3,3]
    const float* enc_b = (const float*)d_in[2];   // [4]
    const float* dec_w = (const float*)d_in[3];
    const float* dec_b = (const float*)d_in[4];
    // d_in[5..7] = epoch(0), T_en(20), T_de(20): fixed by the problem; baked in.

    // Device->device copies into constant bank (graph-capturable memcpy nodes).
    cudaMemcpyToSymbolAsync(c_w, enc_w, 72*sizeof(float), 0,
                            cudaMemcpyDeviceToDevice, 0);
    cudaMemcpyToSymbolAsync(c_w, dec_w, 72*sizeof(float), 72*sizeof(float),
                            cudaMemcpyDeviceToDevice, 0);
    cudaMemcpyToSymbolAsync(c_b, enc_b, 4*sizeof(float), 0,
                            cudaMemcpyDeviceToDevice, 0);
    cudaMemcpyToSymbolAsync(c_b, dec_b, 4*sizeof(float), 16,
                            cudaMemcpyDeviceToDevice, 0);

    void *ph, *pc;
    cudaGetSymbolAddress(&ph, g_h);
    cudaGetSymbolAddress(&pc, g_c);
    float* H0 = (float*)ph;
    float* H1 = H0 + NPIX;
    float* H2 = H0 + 2*NPIX;
    float* C0 = (float*)pc;
    float* C1 = C0 + NPIX;

    const dim3 grid(IMG), block(256);

    // ---------- Encoder: 20 steps over data frames ----------
    lstm_step<true><<<grid, block>>>(data, nullptr, nullptr, H0, C0, 0);
    for (int s = 1; s < 20; ++s){
        const float* xf = data + (size_t)s * NPIX;
        float* hin  = (s & 1) ? H0 : H1;
        float* hout = (s & 1) ? H1 : H0;
        float* cin  = (s & 1) ? C0 : C1;
        float* cout = (s & 1) ? C1 : C0;
        lstm_step<false><<<grid, block>>>(xf, hin, cin, hout, cout, 0);
    }
    // Final encoder h is in H1 (s=19 is odd) -> constant decoder input.

    // ---------- Decoder: 20 steps, fresh (h,c)=0, x = H1 every step ----------
    lstm_step<true><<<grid, block>>>(H1, nullptr, nullptr, H2, C0, 1);
    for (int s = 1; s < 20; ++s){
        float* hin  = (s & 1) ? H2 : H0;
        float* hout = (s & 1) ? H0 : H2;
        float* cin  = (s & 1) ? C0 : C1;
        float* cout = (s & 1) ? C1 : C0;
        if (s == 19) hout = (float*)d_out;   // final decoder h IS the output
        lstm_step<false><<<grid, block>>>(H1, hin, cin, hout, cout, 1);
    }
}